// round 11
// baseline (speedup 1.0000x reference)
#include <cuda_runtime.h>
#include <math.h>
#include <stdint.h>

#define B_    8
#define CIN_  128
#define N_    2048
#define K_    16
#define G_    4
#define L_    192
#define NL_   64
#define CL_   48
#define CNL_  16
#define COUT_ 256
#define NT    16384   // B_*N_
#define TNL   64      // n-tile per CTA in k_nl_main

// ---------------- tf32 rounding (emulate cuBLAS TF32 operand conversion) ----------------
__device__ __forceinline__ float tf32r(float a) {
    uint32_t u;
    asm("cvt.rna.tf32.f32 %0, %1;" : "=r"(u) : "f"(a));
    return __uint_as_float(u);
}

// ---------------- scratch (device globals) ----------------
__device__ float g_cent[B_ * G_ * N_];
__device__ float g_vals[B_ * G_ * K_];
__device__ int   g_inds[B_ * G_ * K_];
__device__ float g_M[B_ * G_ * CNL_ * K_];
__device__ float g_nv2j[B_ * G_ * CNL_ * K_];
__device__ float g_tanhvals[B_ * G_ * K_];

// pipeline intermediates
__device__ float g_lq[L_ * NT];       // [o][ng]
__device__ float g_qt[768 * NT];      // [(d*4+g)][ng]
__device__ float g_kt[256 * NT];      // [(cc*4+g)][ng]
__device__ float g_bcv[G_ * NT];      // [g][ng]
__device__ float g_xa[512 * NT];      // [(g*128+cc)][ng]

// pre-rounded (tf32) weights in access-optimal layouts
__device__ float  rT_Wq[64 * L_];     // [c][o]
__device__ float  r_Wk[L_ * 64];      // [o][cc]
__device__ float  rT_Wv[CIN_ * L_];   // [cc][o]
__device__ float  rT_pe_w2[L_ * L_];  // [c][d]
__device__ float4 g_w1pack[L_];       // {w1x,w1y,w1z,b1}
__device__ float  rT_Wnq[64 * NL_];
__device__ float  rT_Wnk[64 * NL_];
__device__ float  rT_Wnv1[64 * NL_];
__device__ float  rT_Wnv2[64 * NL_];
__device__ float  r_npe_w1[G_ * 3 * CNL_];
__device__ float  r_npe_w2[G_ * CNL_ * CNL_];

// ---------------- kernel: round/transpose weights, zero cent ----------------
__global__ void k_prep(const float* __restrict__ Wq, const float* __restrict__ Wk,
                       const float* __restrict__ Wv,
                       const float* __restrict__ pe_w1, const float* __restrict__ pe_b1,
                       const float* __restrict__ pe_w2,
                       const float* __restrict__ Wnq, const float* __restrict__ Wnk,
                       const float* __restrict__ Wnv1, const float* __restrict__ Wnv2,
                       const float* __restrict__ npe_w1, const float* __restrict__ npe_w2) {
    int tid = blockIdx.x * blockDim.x + threadIdx.x;
    int nth = gridDim.x * blockDim.x;
    for (int i = tid; i < 64 * L_; i += nth) {
        int c = i / L_, o = i % L_;
        rT_Wq[i] = tf32r(Wq[o * 64 + c]);
    }
    for (int i = tid; i < L_ * 64; i += nth) r_Wk[i] = tf32r(Wk[i]);
    for (int i = tid; i < CIN_ * L_; i += nth) {
        int c = i / L_, o = i % L_;
        rT_Wv[i] = tf32r(Wv[o * CIN_ + c]);
    }
    for (int i = tid; i < L_ * L_; i += nth) {
        int c = i / L_, d = i % L_;
        rT_pe_w2[i] = tf32r(pe_w2[d * L_ + c]);
    }
    for (int d = tid; d < L_; d += nth) {
        g_w1pack[d] = make_float4(tf32r(pe_w1[d]), tf32r(pe_w1[L_ + d]),
                                  tf32r(pe_w1[2 * L_ + d]), pe_b1[d]);
    }
    for (int i = tid; i < 64 * NL_; i += nth) {
        int c = i / NL_, o = i % NL_;
        rT_Wnq[i]  = tf32r(Wnq[o * 64 + c]);
        rT_Wnk[i]  = tf32r(Wnk[o * 64 + c]);
        rT_Wnv1[i] = tf32r(Wnv1[o * 64 + c]);
        rT_Wnv2[i] = tf32r(Wnv2[o * 64 + c]);
    }
    for (int i = tid; i < G_ * 3 * CNL_; i += nth)    r_npe_w1[i] = tf32r(npe_w1[i]);
    for (int i = tid; i < G_ * CNL_ * CNL_; i += nth) r_npe_w2[i] = tf32r(npe_w2[i]);
    for (int i = tid; i < B_ * G_ * N_; i += nth) g_cent[i] = 0.f;
}

// ---------------- kernel 1: lq GEMM  (192x16384, K=64) ----------------
#define ABP 20
__global__ __launch_bounds__(192) void k_gemm1(const float* __restrict__ abs_x) {
    __shared__ float absx_s[64 * ABP];
    const int gcol0 = blockIdx.x * 16;
    const int b = gcol0 >> 11;
    const int nloc0 = gcol0 & 2047;
    const int tid = threadIdx.x;

    for (int i = tid; i < 64 * 16; i += 192) {
        int c = i >> 4, n = i & 15;
        absx_s[c * ABP + n] = tf32r(abs_x[(b * 64 + c) * N_ + nloc0 + n]);
    }
    __syncthreads();

    const int o = tid;
    float acc[16];
    #pragma unroll
    for (int j = 0; j < 16; j++) acc[j] = 0.f;
    #pragma unroll 8
    for (int c = 0; c < 64; c++) {
        float w = rT_Wq[c * L_ + o];
        const float4* ap = (const float4*)&absx_s[c * ABP];
        float4 a0 = ap[0], a1 = ap[1], a2 = ap[2], a3 = ap[3];
        acc[0]  += w * a0.x; acc[1]  += w * a0.y; acc[2]  += w * a0.z; acc[3]  += w * a0.w;
        acc[4]  += w * a1.x; acc[5]  += w * a1.y; acc[6]  += w * a1.z; acc[7]  += w * a1.w;
        acc[8]  += w * a2.x; acc[9]  += w * a2.y; acc[10] += w * a2.z; acc[11] += w * a2.w;
        acc[12] += w * a3.x; acc[13] += w * a3.y; acc[14] += w * a3.z; acc[15] += w * a3.w;
    }
    float4* dst = (float4*)&g_lq[(size_t)o * NT + gcol0];
    dst[0] = make_float4(acc[0],  acc[1],  acc[2],  acc[3]);
    dst[1] = make_float4(acc[4],  acc[5],  acc[6],  acc[7]);
    dst[2] = make_float4(acc[8],  acc[9],  acc[10], acc[11]);
    dst[3] = make_float4(acc[12], acc[13], acc[14], acc[15]);
}

// ---------------- kernel 2: qt/kt/bconst GEMMs from lq (n-tile 32) ----------------
#define LQP 36
__global__ __launch_bounds__(256) void k_gemm2(const float* __restrict__ pe_b2) {
    __shared__ float lq_s[L_ * LQP];   // 27.6 KB
    const int gcol0 = blockIdx.x * 32;
    const int tid = threadIdx.x;

    for (int i = tid; i < L_ * 32; i += 256) {
        int o = i >> 5, n = i & 31;
        lq_s[o * LQP + n] = g_lq[(size_t)o * NT + gcol0 + n];
    }
    __syncthreads();

    for (int t = tid; t < 1152; t += 256) {
        if (t < 768) {
            // qt: 4 d-rows x 8 n
            int nq = t & 3, rg = t >> 2;          // rg 0..191
            int g = rg / 48, dgrp = rg % 48;
            int d0 = dgrp * 4;
            float acc[4][8];
            #pragma unroll
            for (int i = 0; i < 4; i++)
                #pragma unroll
                for (int j = 0; j < 8; j++) acc[i][j] = 0.f;
            #pragma unroll 4
            for (int c = 0; c < CL_; c++) {
                float4 w4 = *(const float4*)&rT_pe_w2[(g * CL_ + c) * L_ + d0];
                const float4* lp = (const float4*)&lq_s[(g * CL_ + c) * LQP + nq * 8];
                float4 l0 = lp[0], l1 = lp[1];
                float wv[4] = {w4.x, w4.y, w4.z, w4.w};
                #pragma unroll
                for (int i = 0; i < 4; i++) {
                    acc[i][0] += wv[i] * l0.x; acc[i][1] += wv[i] * l0.y;
                    acc[i][2] += wv[i] * l0.z; acc[i][3] += wv[i] * l0.w;
                    acc[i][4] += wv[i] * l1.x; acc[i][5] += wv[i] * l1.y;
                    acc[i][6] += wv[i] * l1.z; acc[i][7] += wv[i] * l1.w;
                }
            }
            #pragma unroll
            for (int i = 0; i < 4; i++) {
                float4* dst = (float4*)&g_qt[(size_t)((d0 + i) * 4 + g) * NT + gcol0 + nq * 8];
                dst[0] = make_float4(acc[i][0], acc[i][1], acc[i][2], acc[i][3]);
                dst[1] = make_float4(acc[i][4], acc[i][5], acc[i][6], acc[i][7]);
            }
        } else if (t < 1024) {
            // kt: 4 cc-rows x 8 n
            int t2 = t - 768;
            int nq = t2 & 3, rg = t2 >> 2;        // rg 0..63
            int g = rg / 16, cgrp = rg % 16;
            int cc0 = cgrp * 4;
            float acc[4][8];
            #pragma unroll
            for (int i = 0; i < 4; i++)
                #pragma unroll
                for (int j = 0; j < 8; j++) acc[i][j] = 0.f;
            #pragma unroll 4
            for (int c = 0; c < CL_; c++) {
                float4 w4 = *(const float4*)&r_Wk[(g * CL_ + c) * 64 + cc0];
                const float4* lp = (const float4*)&lq_s[(g * CL_ + c) * LQP + nq * 8];
                float4 l0 = lp[0], l1 = lp[1];
                float wv[4] = {w4.x, w4.y, w4.z, w4.w};
                #pragma unroll
                for (int i = 0; i < 4; i++) {
                    acc[i][0] += wv[i] * l0.x; acc[i][1] += wv[i] * l0.y;
                    acc[i][2] += wv[i] * l0.z; acc[i][3] += wv[i] * l0.w;
                    acc[i][4] += wv[i] * l1.x; acc[i][5] += wv[i] * l1.y;
                    acc[i][6] += wv[i] * l1.z; acc[i][7] += wv[i] * l1.w;
                }
            }
            #pragma unroll
            for (int i = 0; i < 4; i++) {
                float4* dst = (float4*)&g_kt[(size_t)((cc0 + i) * 4 + g) * NT + gcol0 + nq * 8];
                dst[0] = make_float4(acc[i][0], acc[i][1], acc[i][2], acc[i][3]);
                dst[1] = make_float4(acc[i][4], acc[i][5], acc[i][6], acc[i][7]);
            }
        } else {
            // bconst: per (g, n)
            int t3 = t - 1024;
            int g = t3 >> 5, n = t3 & 31;
            float sum = 0.f;
            #pragma unroll 8
            for (int c = 0; c < CL_; c++)
                sum += lq_s[(g * CL_ + c) * LQP + n] * pe_b2[g * CL_ + c];
            g_bcv[(size_t)g * NT + gcol0 + n] = sum;
        }
    }
}

// ---------------- kernel 3: middle (rel, scores, softmax, scatter, xa) ----------------
#define TNM   8
#define XPAD  129

struct __align__(16) MidSmem {
    float x[CIN_ * XPAD];        // 66048 B raw x tile
    float qt[L_ * TNM * 4];      // 24576 B  [d][n][g]
    float kt[64 * TNM * 4];      // 8192 B   [cc][n][g]
    float rel[TNM][K_][4];       // 2048 B
    float part[2][G_][TNM][K_];  // 4096 B
    float att[G_][TNM][K_];      // 2048 B
    float attr[G_][TNM][K_];     // 2048 B
    float bc[G_][TNM];           // 128 B
    int   idxs[TNM][K_];         // 512 B
};                               // total 109696 B

__global__ __launch_bounds__(256) void k_mid(
    const float* __restrict__ x,
    const float* __restrict__ points,
    const int*   __restrict__ idx)
{
    extern __shared__ char smem_raw[];
    MidSmem* s = (MidSmem*)smem_raw;

    const int blk = blockIdx.x;
    const int b   = blk >> 8;
    const int n0  = (blk & 255) * TNM;
    const int gcol0 = blk * TNM;
    const int tid = threadIdx.x;

    // ---- phase A: stage x, qt, kt, bc, idxs ----
    {
        const float* xb = x + ((size_t)(b * CIN_) * N_ + n0) * K_;
        for (int i = tid; i < CIN_ * 32; i += 256) {
            int cc = i >> 5, q = i & 31;
            float4 v = *(const float4*)(xb + (size_t)cc * N_ * K_ + q * 4);
            float* dst = &s->x[cc * XPAD + q * 4];
            dst[0] = v.x; dst[1] = v.y; dst[2] = v.z; dst[3] = v.w;
        }
        float* qtf = &s->qt[0];
        for (int i = tid; i < L_ * 4 * TNM; i += 256) {   // 6144
            int row = i >> 3, n = i & 7;                  // row = d*4+g
            int d = row >> 2, g = row & 3;
            qtf[(d * TNM + n) * 4 + g] = g_qt[(size_t)row * NT + gcol0 + n];
        }
        float* ktf = &s->kt[0];
        for (int i = tid; i < 64 * 4 * TNM; i += 256) {   // 2048
            int row = i >> 3, n = i & 7;
            int cc = row >> 2, g = row & 3;
            ktf[(cc * TNM + n) * 4 + g] = g_kt[(size_t)row * NT + gcol0 + n];
        }
        if (tid < G_ * TNM) {
            int g = tid >> 3, n = tid & 7;
            s->bc[g][n] = g_bcv[(size_t)g * NT + gcol0 + n];
        }
        if (tid < TNM * K_) {
            int n = tid >> 4, k = tid & 15;
            s->idxs[n][k] = idx[(b * N_ + n0 + n) * K_ + k];
        }
    }
    __syncthreads();

    // ---- phase R: rel gather ----
    for (int r = tid; r < 3 * TNM * K_; r += 256) {       // 384
        int ax = r >> 7, rem = r & 127, n = rem >> 4, k = rem & 15;
        float p  = points[(b * 3 + ax) * N_ + s->idxs[n][k]];
        float p0 = points[(b * 3 + ax) * N_ + s->idxs[n][0]];
        s->rel[n][k][ax] = tf32r(p - p0);
    }
    __syncthreads();

    // ---- phase D: spe (half d-range) + S_k (half cc-range) per thread ----
    {
        int dq = tid >> 7, r = tid & 127, n = r >> 4, k = r & 15;
        float rx = s->rel[n][k][0], ry = s->rel[n][k][1], rz = s->rel[n][k][2];
        float acc[4] = {0.f, 0.f, 0.f, 0.f};
        const float* qtf = &s->qt[0];
        #pragma unroll 4
        for (int dd = 0; dd < 96; dd++) {
            int d = dq * 96 + dd;
            float4 wp = g_w1pack[d];
            float hv = rx * wp.x + ry * wp.y + rz * wp.z + wp.w;
            hv = hv > 0.f ? hv : 0.f;
            hv = tf32r(hv);
            float4 q4 = *(const float4*)&qtf[(d * TNM + n) * 4];
            acc[0] += q4.x * hv; acc[1] += q4.y * hv;
            acc[2] += q4.z * hv; acc[3] += q4.w * hv;
        }
        const float* ktf = &s->kt[0];
        #pragma unroll 4
        for (int cc = dq * 32; cc < dq * 32 + 32; cc++) {
            float lo = s->x[cc * XPAD + n * 16 + k];
            float hi = s->x[(cc + 64) * XPAD + n * 16 + k];
            float xsv = tf32r(lo + hi);
            float4 k4 = *(const float4*)&ktf[(cc * TNM + n) * 4];
            acc[0] += k4.x * xsv; acc[1] += k4.y * xsv;
            acc[2] += k4.z * xsv; acc[3] += k4.w * xsv;
        }
        #pragma unroll
        for (int g = 0; g < 4; g++) s->part[dq][g][n][k] = acc[g];
    }
    __syncthreads();

    // ---- phase E: combine + softmax ----
    if (tid < G_ * TNM) {
        int g = tid >> 3, n = tid & 7;
        float sc[K_];
        float m = -1e30f;
        #pragma unroll
        for (int k = 0; k < K_; k++) {
            sc[k] = s->part[0][g][n][k] + s->part[1][g][n][k] + s->bc[g][n];
            m = fmaxf(m, sc[k]);
        }
        float sum = 0.f;
        #pragma unroll
        for (int k = 0; k < K_; k++) { sc[k] = expf(sc[k] - m); sum += sc[k]; }
        float inv = 1.f / sum;
        #pragma unroll
        for (int k = 0; k < K_; k++) {
            float a = sc[k] * inv;
            s->att[g][n][k]  = a;
            s->attr[g][n][k] = tf32r(a);
        }
    }
    __syncthreads();

    // ---- phase F: scatter + xa -> global ----
    {
        for (int t = tid; t < G_ * TNM * K_; t += 256) {  // 512 atomics
            int g = t >> 7, rem = t & 127, n = rem >> 4, k = rem & 15;
            atomicAdd(&g_cent[(b * G_ + g) * N_ + s->idxs[n][k]], s->att[g][n][k]);
        }
        int cc = tid & 127, nset = tid >> 7;              // nset 0..1
        float xacc[4][4];
        #pragma unroll
        for (int g = 0; g < 4; g++)
            #pragma unroll
            for (int j = 0; j < 4; j++) xacc[g][j] = 0.f;
        for (int ni = 0; ni < 4; ni++) {
            int n = nset * 4 + ni;
            float a0 = 0.f, a1 = 0.f, a2 = 0.f, a3 = 0.f;
            #pragma unroll
            for (int k = 0; k < K_; k++) {
                float xv = tf32r(s->x[cc * XPAD + n * 16 + k]);
                a0 += s->attr[0][n][k] * xv;
                a1 += s->attr[1][n][k] * xv;
                a2 += s->attr[2][n][k] * xv;
                a3 += s->attr[3][n][k] * xv;
            }
            xacc[0][ni] = a0; xacc[1][ni] = a1; xacc[2][ni] = a2; xacc[3][ni] = a3;
        }
        #pragma unroll
        for (int g = 0; g < 4; g++) {
            *(float4*)&g_xa[(size_t)(g * CIN_ + cc) * NT + gcol0 + nset * 4] =
                make_float4(xacc[g][0], xacc[g][1], xacc[g][2], xacc[g][3]);
        }
    }
}

// ---------------- kernel 4: out-local GEMM (Wv . xa), n-tile 16 ----------------
#define XAP 20
__global__ __launch_bounds__(192) void k_gemm3(float* __restrict__ out) {
    __shared__ float xa_s[512 * XAP];   // 40960 B
    const int gcol0 = blockIdx.x * 16;
    const int b = gcol0 >> 11;
    const int nloc0 = gcol0 & 2047;
    const int tid = threadIdx.x;

    for (int i = tid; i < 512 * 16; i += 192) {
        int row = i >> 4, n = i & 15;
        xa_s[row * XAP + n] = g_xa[(size_t)row * NT + gcol0 + n];
    }
    __syncthreads();

    const int o = tid;
    const int g = o / CL_;
    float acc[16];
    #pragma unroll
    for (int j = 0; j < 16; j++) acc[j] = 0.f;
    #pragma unroll 8
    for (int cc = 0; cc < CIN_; cc++) {
        float w = rT_Wv[cc * L_ + o];
        const float4* xp = (const float4*)&xa_s[(g * CIN_ + cc) * XAP];
        float4 x0 = xp[0], x1 = xp[1], x2 = xp[2], x3 = xp[3];
        acc[0]  += w * x0.x; acc[1]  += w * x0.y; acc[2]  += w * x0.z; acc[3]  += w * x0.w;
        acc[4]  += w * x1.x; acc[5]  += w * x1.y; acc[6]  += w * x1.z; acc[7]  += w * x1.w;
        acc[8]  += w * x2.x; acc[9]  += w * x2.y; acc[10] += w * x2.z; acc[11] += w * x2.w;
        acc[12] += w * x3.x; acc[13] += w * x3.y; acc[14] += w * x3.z; acc[15] += w * x3.w;
    }
    float4* dst = (float4*)&out[((size_t)(b * COUT_ + o)) * N_ + nloc0];
    dst[0] = make_float4(acc[0],  acc[1],  acc[2],  acc[3]);
    dst[1] = make_float4(acc[4],  acc[5],  acc[6],  acc[7]);
    dst[2] = make_float4(acc[8],  acc[9],  acc[10], acc[11]);
    dst[3] = make_float4(acc[12], acc[13], acc[14], acc[15]);
}

// ---------------- kernel: top-16 per (b,g), desc, tie -> lower index ----------------
__global__ __launch_bounds__(256) void k_topk() {
    const int bg  = blockIdx.x;
    const int tid = threadIdx.x;
    __shared__ float v_s[N_];
    __shared__ float rv[256];
    __shared__ int   ri[256];

    for (int i = tid; i < N_; i += 256) v_s[i] = g_cent[bg * N_ + i];
    __syncthreads();

    for (int t = 0; t < K_; t++) {
        float bv = -1e30f; int bi = N_;
        for (int i = tid; i < N_; i += 256) {
            float v = v_s[i];
            if (v > bv || (v == bv && i < bi)) { bv = v; bi = i; }
        }
        rv[tid] = bv; ri[tid] = bi;
        __syncthreads();
        for (int sd = 128; sd > 0; sd >>= 1) {
            if (tid < sd) {
                if (rv[tid + sd] > rv[tid] ||
                    (rv[tid + sd] == rv[tid] && ri[tid + sd] < ri[tid])) {
                    rv[tid] = rv[tid + sd]; ri[tid] = ri[tid + sd];
                }
            }
            __syncthreads();
        }
        if (tid == 0) {
            g_vals[bg * K_ + t] = rv[0];
            g_inds[bg * K_ + t] = ri[0];
            v_s[ri[0]] = -1e30f;
        }
        __syncthreads();
    }
}

// ---------------- kernel: non-local prep per (b,g) ----------------
__global__ __launch_bounds__(256) void k_nl_prep(
    const float* __restrict__ abs_x,
    const float* __restrict__ points,
    const float* __restrict__ npe_b1,
    const float* __restrict__ npe_b2)
{
    const int bg = blockIdx.x;
    const int b = bg / G_, g = bg % G_;
    const int tid = threadIdx.x;

    __shared__ int   inds_s[K_];
    __shared__ float rel_s[3][K_];
    __shared__ float h2_s[K_][CNL_];

    if (tid < K_) {
        inds_s[tid] = g_inds[bg * K_ + tid];
        g_tanhvals[bg * K_ + tid] = tanhf(g_vals[bg * K_ + tid]);
    }
    __syncthreads();
    if (tid < 3 * K_) {
        int c = tid / K_, j = tid % K_;
        rel_s[c][j] = tf32r(points[(b * 3 + c) * N_ + inds_s[j]]
                          - points[(b * 3 + c) * N_ + inds_s[0]]);
    }
    __syncthreads();
    {
        int j = tid / CNL_, d = tid % CNL_;
        float h = npe_b1[g * CNL_ + d];
        #pragma unroll
        for (int c = 0; c < 3; c++) h += rel_s[c][j] * r_npe_w1[(g * 3 + c) * CNL_ + d];
        h2_s[j][d] = tf32r(h > 0.f ? h : 0.f);
    }
    __syncthreads();
    {
        int c = tid / K_, j = tid % K_;
        float pe = npe_b2[g * CNL_ + c];
        #pragma unroll
        for (int d = 0; d < CNL_; d++) pe += h2_s[j][d] * r_npe_w2[(g * CNL_ + d) * CNL_ + c];
        int nn = inds_s[j];
        float nk = 0.f, nv2 = 0.f;
        const int row = g * CNL_ + c;
        #pragma unroll 8
        for (int cc = 0; cc < 64; cc++) {
            float a = tf32r(abs_x[(b * 64 + cc) * N_ + nn]);
            nk  += rT_Wnk[cc * NL_ + row]  * a;
            nv2 += rT_Wnv2[cc * NL_ + row] * a;
        }
        g_M[bg * CNL_ * K_ + c * K_ + j]    = nk + pe;
        g_nv2j[bg * CNL_ * K_ + c * K_ + j] = nv2;
    }
}

// ---------------- kernel: non-local main (smem-staged, shuffle subgroups) ----------------
struct __align__(16) NLSmem {
    float wnq[64 * 64];
    float wnv1[64 * 64];
    float wnv2[64 * 64];
    float M[G_][CNL_ * K_];
    float nv2jT[G_][K_ * CNL_];
    float tv[G_ * K_];
    float a2[64][4];
    float outbuf[64 * 65];
};

__global__ __launch_bounds__(256) void k_nl_main(
    const float* __restrict__ abs_x,
    float*       __restrict__ out)
{
    extern __shared__ char smraw[];
    NLSmem* s = (NLSmem*)smraw;

    const int blk = blockIdx.x;
    const int b   = blk / (N_ / TNL);
    const int n0  = (blk % (N_ / TNL)) * TNL;
    const int tid = threadIdx.x;
    const int warp  = tid >> 5;
    const int half  = (tid >> 4) & 1;
    const int c     = tid & 15;
    const int g     = (warp & 1) * 2 + half;
    const int nslot = warp >> 1;
    const int o     = g * CNL_ + c;

    for (int i = tid; i < 64 * 64; i += 256) {
        s->wnq[i]  = rT_Wnq[i];
        s->wnv1[i] = rT_Wnv1[i];
        s->wnv2[i] = rT_Wnv2[i];
    }
    for (int i = tid; i < G_ * CNL_ * K_; i += 256) {
        float mv = tf32r(g_M[b * G_ * CNL_ * K_ + i]);
        s->M[0][i] = mv;
        int gg = i >> 8, rem = i & 255, cc2 = rem >> 4, jj = rem & 15;
        s->nv2jT[gg][jj * 16 + cc2] = tf32r(g_nv2j[b * G_ * CNL_ * K_ + i]);
    }
    if (tid < G_ * K_) s->tv[tid] = g_tanhvals[b * G_ * K_ + tid];
    __syncthreads();

    const float tvj = s->tv[g * K_ + c];

    for (int it = 0; it < TNL / 4; it++) {
        const int nb = n0 + it * 4;
        {
            int cc = tid >> 2, nn = tid & 3;
            s->a2[cc][nn] = tf32r(abs_x[(b * 64 + cc) * N_ + nb + nn]);
        }
        __syncthreads();

        float nq = 0.f, nv1 = 0.f, nv2 = 0.f;
        #pragma unroll 8
        for (int cc = 0; cc < 64; cc++) {
            float a = s->a2[cc][nslot];
            nq  += s->wnq[cc * 64 + o]  * a;
            nv1 += s->wnv1[cc * 64 + o] * a;
            nv2 += s->wnv2[cc * 64 + o] * a;
        }
        float nqr = tf32r(nq);

        float sc = 0.f;
        const float* Mg = s->M[g];
        #pragma unroll
        for (int c2 = 0; c2 < CNL_; c2++) {
            float v = __shfl_sync(0xffffffffu, nqr, c2, 16);
            sc += v * Mg[c2 * 16 + c];
        }
        float m = -1e30f;
        #pragma unroll
        for (int j = 0; j < K_; j++) m = fmaxf(m, __shfl_sync(0xffffffffu, sc, j, 16));
        float e = expf(sc - m);
        float sum = 0.f;
        #pragma unroll
        for (int j = 0; j < K_; j++) sum += __shfl_sync(0xffffffffu, e, j, 16);
        float inv = 1.f / sum;
        float w = e * inv * tvj;
        float ws = 0.f;
        #pragma unroll
        for (int j = 0; j < K_; j++) ws += __shfl_sync(0xffffffffu, w, j, 16);

        float og = (nv1 - nv2) * ws;
        const float* nvg = s->nv2jT[g];
        #pragma unroll
        for (int j = 0; j < K_; j++) {
            float wj = tf32r(__shfl_sync(0xffffffffu, w, j, 16));
            og += wj * nvg[j * 16 + c];
        }
        s->outbuf[o * 65 + it * 4 + nslot] = og;
        __syncthreads();
    }

    for (int t = tid; t < 64 * 16; t += 256) {
        int o2 = t >> 4, q = t & 15;
        const float* rp = &s->outbuf[o2 * 65 + q * 4];
        float4 v = make_float4(rp[0], rp[1], rp[2], rp[3]);
        *(float4*)&out[((size_t)(b * COUT_ + L_ + o2)) * N_ + n0 + q * 4] = v;
    }
}

// ---------------- launcher ----------------
extern "C" void kernel_launch(void* const* d_in, const int* in_sizes, int n_in,
                              void* d_out, int out_size) {
    const float* x      = (const float*)d_in[0];
    const float* abs_x  = (const float*)d_in[1];
    const float* points = (const float*)d_in[2];
    const float* Wq     = (const float*)d_in[3];
    const float* Wk     = (const float*)d_in[4];
    const float* Wv     = (const float*)d_in[5];
    const float* Wnq    = (const float*)d_in[6];
    const float* Wnk    = (const float*)d_in[7];
    const float* Wnv1   = (const float*)d_in[8];
    const float* Wnv2   = (const float*)d_in[9];
    const float* pe_w1  = (const float*)d_in[10];
    const float* pe_b1  = (const float*)d_in[11];
    const float* pe_w2  = (const float*)d_in[12];
    const float* pe_b2  = (const float*)d_in[13];
    const float* npe_w1 = (const float*)d_in[14];
    const float* npe_b1 = (const float*)d_in[15];
    const float* npe_w2 = (const float*)d_in[16];
    const float* npe_b2 = (const float*)d_in[17];
    const int*   idx    = (const int*)d_in[18];
    float* out = (float*)d_out;

    static int smem_set = 0;
    if (!smem_set) {
        cudaFuncSetAttribute(k_mid, cudaFuncAttributeMaxDynamicSharedMemorySize,
                             (int)sizeof(MidSmem));
        cudaFuncSetAttribute(k_nl_main, cudaFuncAttributeMaxDynamicSharedMemorySize,
                             (int)sizeof(NLSmem));
        smem_set = 1;
    }

    k_prep<<<128, 256>>>(Wq, Wk, Wv, pe_w1, pe_b1, pe_w2,
                         Wnq, Wnk, Wnv1, Wnv2, npe_w1, npe_w2);
    k_gemm1<<<NT / 16, 192>>>(abs_x);
    k_gemm2<<<NT / 32, 256>>>(pe_b2);
    k_mid<<<NT / TNM, 256, sizeof(MidSmem)>>>(x, points, idx);
    k_gemm3<<<NT / 16, 192>>>(out);
    k_topk<<<B_ * G_, 256>>>();
    k_nl_prep<<<B_ * G_, 256>>>(abs_x, points, npe_b1, npe_b2);
    k_nl_main<<<B_ * (N_ / TNL), 256, sizeof(NLSmem)>>>(abs_x, out);
}

// round 13
// speedup vs baseline: 1.2010x; 1.2010x over previous
#include <cuda_runtime.h>
#include <math.h>
#include <stdint.h>

#define B_    8
#define CIN_  128
#define N_    2048
#define K_    16
#define G_    4
#define L_    192
#define NL_   64
#define CL_   48
#define CNL_  16
#define COUT_ 256
#define TN    8       // n-tile per CTA in k_local
#define THR   512
#define TNL   64      // n-tile per CTA in k_nl_main

// ---------------- tf32 rounding (emulate cuBLAS TF32 operand conversion) ----------------
__device__ __forceinline__ float tf32r(float a) {
    uint32_t u;
    asm("cvt.rna.tf32.f32 %0, %1;" : "=r"(u) : "f"(a));
    return __uint_as_float(u);
}

// ---------------- scratch (device globals) ----------------
__device__ float g_cent[B_ * G_ * N_];
__device__ float g_vals[B_ * G_ * K_];
__device__ int   g_inds[B_ * G_ * K_];
__device__ float g_M[B_ * G_ * CNL_ * K_];
__device__ float g_nv2j[B_ * G_ * CNL_ * K_];
__device__ float g_tanhvals[B_ * G_ * K_];

// pre-rounded (tf32) weights in access-optimal layouts
__device__ float  rT_Wq[64 * L_];     // [c][o]
__device__ float  r_Wk[L_ * 64];      // [o][cc]
__device__ float  rT_Wv[CIN_ * L_];   // [cc][o]
__device__ float  rT_pe_w2[L_ * L_];  // [c][d]
__device__ float4 g_w1pack[L_];       // {w1x,w1y,w1z,b1}
__device__ float  rT_Wnq[64 * NL_];
__device__ float  rT_Wnk[64 * NL_];
__device__ float  rT_Wnv1[64 * NL_];
__device__ float  rT_Wnv2[64 * NL_];
__device__ float  r_npe_w1[G_ * 3 * CNL_];
__device__ float  r_npe_w2[G_ * CNL_ * CNL_];

// ---------------- kernel: round/transpose weights, zero cent ----------------
__global__ void k_prep(const float* __restrict__ Wq, const float* __restrict__ Wk,
                       const float* __restrict__ Wv,
                       const float* __restrict__ pe_w1, const float* __restrict__ pe_b1,
                       const float* __restrict__ pe_w2,
                       const float* __restrict__ Wnq, const float* __restrict__ Wnk,
                       const float* __restrict__ Wnv1, const float* __restrict__ Wnv2,
                       const float* __restrict__ npe_w1, const float* __restrict__ npe_w2) {
    int tid = blockIdx.x * blockDim.x + threadIdx.x;
    int nth = gridDim.x * blockDim.x;
    for (int i = tid; i < 64 * L_; i += nth) {
        int c = i / L_, o = i % L_;
        rT_Wq[i] = tf32r(Wq[o * 64 + c]);
    }
    for (int i = tid; i < L_ * 64; i += nth) r_Wk[i] = tf32r(Wk[i]);
    for (int i = tid; i < CIN_ * L_; i += nth) {
        int c = i / L_, o = i % L_;
        rT_Wv[i] = tf32r(Wv[o * CIN_ + c]);
    }
    for (int i = tid; i < L_ * L_; i += nth) {
        int c = i / L_, d = i % L_;
        rT_pe_w2[i] = tf32r(pe_w2[d * L_ + c]);
    }
    for (int d = tid; d < L_; d += nth) {
        g_w1pack[d] = make_float4(tf32r(pe_w1[d]), tf32r(pe_w1[L_ + d]),
                                  tf32r(pe_w1[2 * L_ + d]), pe_b1[d]);
    }
    for (int i = tid; i < 64 * NL_; i += nth) {
        int c = i / NL_, o = i % NL_;
        rT_Wnq[i]  = tf32r(Wnq[o * 64 + c]);
        rT_Wnk[i]  = tf32r(Wnk[o * 64 + c]);
        rT_Wnv1[i] = tf32r(Wnv1[o * 64 + c]);
        rT_Wnv2[i] = tf32r(Wnv2[o * 64 + c]);
    }
    for (int i = tid; i < G_ * 3 * CNL_; i += nth)    r_npe_w1[i] = tf32r(npe_w1[i]);
    for (int i = tid; i < G_ * CNL_ * CNL_; i += nth) r_npe_w2[i] = tf32r(npe_w2[i]);
    for (int i = tid; i < B_ * G_ * N_; i += nth) g_cent[i] = 0.f;
}

// ---------------- k_local smem (TN=8, THR=512) ----------------
#define XPAD  129     // x row pad (odd -> conflict-free column access)
#define QPAD  36      // qt/kt row pad: multiple of 4 -> aligned float4 reads in D
#define LPAD  12      // lq row pad: 48B, float4-aligned at offsets 0/16B
#define XAPAD 12      // xa row pad (overlays qt+kt+lq)

struct __align__(16) LocalSmem {
    float x[CIN_ * XPAD];        // raw x tile, 66048 B
    float qt[96 * QPAD];         // [dloc][n*4+g], 13824 B (xa overlay starts here)
    float kt[64 * QPAD];         // [cc][n*4+g], 9216 B
    float lq[L_ * LPAD];         // [o][n], 9216 B
    float absx[64][TN];          // 2048 B
    float rel[TN][K_][4];        // 2048 B
    float part[4][G_][TN][K_];   // 8192 B
    float att[G_][TN][K_];       // raw att, 2048 B
    float bconst[G_][TN];        // 128 B
    int   idxs[TN][K_];          // 512 B
};                               // total 113280 B

// ---------------- kernel 1: fused local branch (regrouped, 32 warps/SM) ----------------
__global__ __launch_bounds__(THR) void k_local(
    const float* __restrict__ x,
    const float* __restrict__ abs_x,
    const float* __restrict__ points,
    const float* __restrict__ pe_b2,
    const int*   __restrict__ idx,
    float*       __restrict__ out)
{
    extern __shared__ char smem_raw[];
    LocalSmem* s = (LocalSmem*)smem_raw;

    const int blk = blockIdx.x;
    const int b   = blk >> 8;              // / 256
    const int n0  = (blk & 255) * TN;
    const int tid = threadIdx.x;

    // ================= phase A: loads =================
    {
        const float* xb = x + ((size_t)(b * CIN_) * N_ + n0) * K_;
        for (int i = tid; i < CIN_ * 32; i += THR) {   // 32 float4 per cc row
            int cc = i >> 5, q = i & 31;
            float4 v = *(const float4*)(xb + (size_t)cc * N_ * K_ + q * 4);
            float* dst = &s->x[cc * XPAD + q * 4];
            dst[0] = v.x; dst[1] = v.y; dst[2] = v.z; dst[3] = v.w;
        }
        if (tid < 64 * TN) {
            int c = tid >> 3, n = tid & 7;
            s->absx[c][n] = tf32r(abs_x[(b * 64 + c) * N_ + n0 + n]);
        }
        if (tid < TN * K_) {
            int n = tid >> 4, k = tid & 15;
            s->idxs[n][k] = idx[(b * N_ + n0 + n) * K_ + k];
        }
    }
    __syncthreads();

    // ================= phase B: lq (384 thr, 4n each) + rel gather (128 thr) =================
    if (tid < 384) {
        const int o = tid % 192, nh = tid / 192;
        float a0 = 0.f, a1 = 0.f, a2 = 0.f, a3 = 0.f;
        #pragma unroll 8
        for (int c = 0; c < 64; c++) {
            float w = rT_Wq[c * L_ + o];
            float4 av = *(const float4*)&s->absx[c][nh * 4];
            a0 += w * av.x; a1 += w * av.y; a2 += w * av.z; a3 += w * av.w;
        }
        *(float4*)&s->lq[o * LPAD + nh * 4] = make_float4(a0, a1, a2, a3);
    } else {
        int t = tid - 384;
        for (int r = t; r < 3 * TN * K_; r += 128) {     // 384 elems
            int ax = r >> 7, rem = r & 127, n = rem >> 4, k = rem & 15;
            float p  = points[(b * 3 + ax) * N_ + s->idxs[n][k]];
            float p0 = points[(b * 3 + ax) * N_ + s->idxs[n][0]];
            s->rel[n][k][ax] = tf32r(p - p0);
        }
    }
    __syncthreads();

    // ---- qt task: (g, dloc, nh) -> 4 n ----
    auto qt_task = [&](int g, int dloc, int nh, int dbase) {
        int d = dbase + dloc;
        float a0 = 0.f, a1 = 0.f, a2 = 0.f, a3 = 0.f;
        const float* wcol = &rT_pe_w2[(g * CL_) * L_ + d];
        #pragma unroll 8
        for (int c = 0; c < CL_; c++) {
            float w = wcol[c * L_];
            float4 lv = *(const float4*)&s->lq[(g * CL_ + c) * LPAD + nh * 4];
            a0 += w * lv.x; a1 += w * lv.y; a2 += w * lv.z; a3 += w * lv.w;
        }
        float* qp = &s->qt[dloc * QPAD + nh * 16 + g];
        qp[0] = a0; qp[4] = a1; qp[8] = a2; qp[12] = a3;
    };
    // ---- kt task: (g, cc, nh) -> 4 n ----
    auto kt_task = [&](int g, int cc, int nh) {
        float a0 = 0.f, a1 = 0.f, a2 = 0.f, a3 = 0.f;
        #pragma unroll 8
        for (int c = 0; c < CL_; c++) {
            float w = r_Wk[(g * CL_ + c) * 64 + cc];
            float4 lv = *(const float4*)&s->lq[(g * CL_ + c) * LPAD + nh * 4];
            a0 += w * lv.x; a1 += w * lv.y; a2 += w * lv.z; a3 += w * lv.w;
        }
        float* kp = &s->kt[cc * QPAD + nh * 16 + g];
        kp[0] = a0; kp[4] = a1; kp[8] = a2; kp[12] = a3;
    };

    // ================= phase C0: qt(d<96) [768] + kt(cc<32) [256] =================
    for (int t = tid; t < 1024; t += THR) {
        if (t < 768) {
            int nh = t & 1, rg = t >> 1;          // rg 0..383
            qt_task(rg / 96, rg % 96, nh, 0);
        } else {
            int t2 = t - 768;                     // 0..255
            int g = t2 >> 6, rem = t2 & 63;
            kt_task(g, rem >> 1, rem & 1);
        }
    }
    __syncthreads();

    // ================= phase D0: spe(d<96, quarter per dq) + S_k(cc<32, 8 per dq) =================
    {
        int dq = tid >> 7;                        // 0..3
        int r = tid & 127, n = r >> 4, k = r & 15;
        float rx = s->rel[n][k][0], ry = s->rel[n][k][1], rz = s->rel[n][k][2];
        float a0 = 0.f, a1 = 0.f, a2 = 0.f, a3 = 0.f;
        #pragma unroll 4
        for (int dd = 0; dd < 24; dd++) {
            int d = dq * 24 + dd;
            float4 wp = g_w1pack[d];
            float hv = rx * wp.x + ry * wp.y + rz * wp.z + wp.w;
            hv = hv > 0.f ? hv : 0.f;
            hv = tf32r(hv);
            float4 q4 = *(const float4*)&s->qt[d * QPAD + n * 4];
            a0 += q4.x * hv; a1 += q4.y * hv; a2 += q4.z * hv; a3 += q4.w * hv;
        }
        #pragma unroll 4
        for (int cc = dq * 8; cc < dq * 8 + 8; cc++) {   // cc 0..31 only (kt from C0)
            float xsv = tf32r(s->x[cc * XPAD + n * 16 + k]
                            + s->x[(cc + 64) * XPAD + n * 16 + k]);
            float4 k4 = *(const float4*)&s->kt[cc * QPAD + n * 4];
            a0 += k4.x * xsv; a1 += k4.y * xsv; a2 += k4.z * xsv; a3 += k4.w * xsv;
        }
        s->part[dq][0][n][k] = a0; s->part[dq][1][n][k] = a1;
        s->part[dq][2][n][k] = a2; s->part[dq][3][n][k] = a3;
    }
    __syncthreads();

    // ================= phase C1: qt(d>=96) [768] + kt(cc>=32) [256] + bconst [32] =================
    for (int t = tid; t < 1056; t += THR) {
        if (t < 768) {
            int nh = t & 1, rg = t >> 1;
            qt_task(rg / 96, rg % 96, nh, 96);
        } else if (t < 1024) {
            int t2 = t - 768;
            int g = t2 >> 6, rem = t2 & 63;
            kt_task(g, 32 + (rem >> 1), rem & 1);
        } else {
            int t3 = t - 1024;
            int g = t3 >> 3, n = t3 & 7;
            float sum = 0.f;
            #pragma unroll 8
            for (int c = 0; c < CL_; c++)
                sum += s->lq[(g * CL_ + c) * LPAD + n] * pe_b2[g * CL_ + c];
            s->bconst[g][n] = sum;
        }
    }
    __syncthreads();

    // ================= phase D1: spe(d>=96) + S_k(cc>=32, 8 per dq), accumulate =================
    {
        int dq = tid >> 7;
        int r = tid & 127, n = r >> 4, k = r & 15;
        float rx = s->rel[n][k][0], ry = s->rel[n][k][1], rz = s->rel[n][k][2];
        float a0 = 0.f, a1 = 0.f, a2 = 0.f, a3 = 0.f;
        #pragma unroll 4
        for (int dd = 0; dd < 24; dd++) {
            int dloc = dq * 24 + dd;
            float4 wp = g_w1pack[96 + dloc];
            float hv = rx * wp.x + ry * wp.y + rz * wp.z + wp.w;
            hv = hv > 0.f ? hv : 0.f;
            hv = tf32r(hv);
            float4 q4 = *(const float4*)&s->qt[dloc * QPAD + n * 4];
            a0 += q4.x * hv; a1 += q4.y * hv; a2 += q4.z * hv; a3 += q4.w * hv;
        }
        #pragma unroll 4
        for (int cc = 32 + dq * 8; cc < 32 + dq * 8 + 8; cc++) {  // cc 32..63 (kt from C1)
            float xsv = tf32r(s->x[cc * XPAD + n * 16 + k]
                            + s->x[(cc + 64) * XPAD + n * 16 + k]);
            float4 k4 = *(const float4*)&s->kt[cc * QPAD + n * 4];
            a0 += k4.x * xsv; a1 += k4.y * xsv; a2 += k4.z * xsv; a3 += k4.w * xsv;
        }
        s->part[dq][0][n][k] += a0; s->part[dq][1][n][k] += a1;
        s->part[dq][2][n][k] += a2; s->part[dq][3][n][k] += a3;
    }
    __syncthreads();

    // ================= phase E: combine + softmax (32 tasks) =================
    if (tid < G_ * TN) {
        int g = tid >> 3, n = tid & 7;
        float sc[K_];
        float m = -1e30f;
        #pragma unroll
        for (int k = 0; k < K_; k++) {
            sc[k] = s->part[0][g][n][k] + s->part[1][g][n][k]
                  + s->part[2][g][n][k] + s->part[3][g][n][k] + s->bconst[g][n];
            m = fmaxf(m, sc[k]);
        }
        float sum = 0.f;
        #pragma unroll
        for (int k = 0; k < K_; k++) { sc[k] = expf(sc[k] - m); sum += sc[k]; }
        float inv = 1.f / sum;
        #pragma unroll
        for (int k = 0; k < K_; k++) s->att[g][n][k] = sc[k] * inv;
    }
    __syncthreads();

    // ================= phase F: scatter (1 atomic/thread) + xa =================
    {
        {
            int g = tid >> 7, rem = tid & 127, n = rem >> 4, k = rem & 15;
            atomicAdd(&g_cent[(b * G_ + g) * N_ + s->idxs[n][k]], s->att[g][n][k]);
        }
        float* xa = &s->qt[0];   // overlays qt+kt+lq (32256B >= 512*12*4=24576B)
        int cc = tid & 127, nset = tid >> 7;              // nset 0..3, 2 n each
        for (int ni = 0; ni < 2; ni++) {
            int n = nset * 2 + ni;
            float a0 = 0.f, a1 = 0.f, a2 = 0.f, a3 = 0.f;
            #pragma unroll
            for (int k = 0; k < K_; k++) {
                float xv = tf32r(s->x[cc * XPAD + n * 16 + k]);
                a0 += tf32r(s->att[0][n][k]) * xv;
                a1 += tf32r(s->att[1][n][k]) * xv;
                a2 += tf32r(s->att[2][n][k]) * xv;
                a3 += tf32r(s->att[3][n][k]) * xv;
            }
            xa[(0 * CIN_ + cc) * XAPAD + n] = a0;
            xa[(1 * CIN_ + cc) * XAPAD + n] = a1;
            xa[(2 * CIN_ + cc) * XAPAD + n] = a2;
            xa[(3 * CIN_ + cc) * XAPAD + n] = a3;
        }
    }
    __syncthreads();

    // ================= phase G: out = Wv^T-dot(xa) (384 thr, 4n each) + direct store =================
    if (tid < 384) {
        const float* xa = &s->qt[0];
        int o = tid % 192, nh = tid / 192;
        int g = o / CL_;
        float a0 = 0.f, a1 = 0.f, a2 = 0.f, a3 = 0.f;
        #pragma unroll 8
        for (int cc = 0; cc < CIN_; cc++) {
            float w = rT_Wv[cc * L_ + o];
            float4 xv = *(const float4*)&xa[(g * CIN_ + cc) * XAPAD + nh * 4];
            a0 += w * xv.x; a1 += w * xv.y; a2 += w * xv.z; a3 += w * xv.w;
        }
        *(float4*)&out[((size_t)(b * COUT_ + o)) * N_ + n0 + nh * 4] =
            make_float4(a0, a1, a2, a3);
    }
}

// ---------------- kernel 2: top-16 per (b,g), desc, tie -> lower index ----------------
__global__ __launch_bounds__(256) void k_topk() {
    const int bg  = blockIdx.x;
    const int tid = threadIdx.x;
    __shared__ float v_s[N_];
    __shared__ float rv[256];
    __shared__ int   ri[256];

    for (int i = tid; i < N_; i += 256) v_s[i] = g_cent[bg * N_ + i];
    __syncthreads();

    for (int t = 0; t < K_; t++) {
        float bv = -1e30f; int bi = N_;
        for (int i = tid; i < N_; i += 256) {
            float v = v_s[i];
            if (v > bv || (v == bv && i < bi)) { bv = v; bi = i; }
        }
        rv[tid] = bv; ri[tid] = bi;
        __syncthreads();
        for (int sd = 128; sd > 0; sd >>= 1) {
            if (tid < sd) {
                if (rv[tid + sd] > rv[tid] ||
                    (rv[tid + sd] == rv[tid] && ri[tid + sd] < ri[tid])) {
                    rv[tid] = rv[tid + sd]; ri[tid] = ri[tid + sd];
                }
            }
            __syncthreads();
        }
        if (tid == 0) {
            g_vals[bg * K_ + t] = rv[0];
            g_inds[bg * K_ + t] = ri[0];
            v_s[ri[0]] = -1e30f;
        }
        __syncthreads();
    }
}

// ---------------- kernel 3: non-local prep per (b,g) ----------------
__global__ __launch_bounds__(256) void k_nl_prep(
    const float* __restrict__ abs_x,
    const float* __restrict__ points,
    const float* __restrict__ npe_b1,
    const float* __restrict__ npe_b2)
{
    const int bg = blockIdx.x;
    const int b = bg / G_, g = bg % G_;
    const int tid = threadIdx.x;

    __shared__ int   inds_s[K_];
    __shared__ float rel_s[3][K_];
    __shared__ float h2_s[K_][CNL_];

    if (tid < K_) {
        inds_s[tid] = g_inds[bg * K_ + tid];
        g_tanhvals[bg * K_ + tid] = tanhf(g_vals[bg * K_ + tid]);
    }
    __syncthreads();
    if (tid < 3 * K_) {
        int c = tid / K_, j = tid % K_;
        rel_s[c][j] = tf32r(points[(b * 3 + c) * N_ + inds_s[j]]
                          - points[(b * 3 + c) * N_ + inds_s[0]]);
    }
    __syncthreads();
    {
        int j = tid / CNL_, d = tid % CNL_;
        float h = npe_b1[g * CNL_ + d];
        #pragma unroll
        for (int c = 0; c < 3; c++) h += rel_s[c][j] * r_npe_w1[(g * 3 + c) * CNL_ + d];
        h2_s[j][d] = tf32r(h > 0.f ? h : 0.f);
    }
    __syncthreads();
    {
        int c = tid / K_, j = tid % K_;
        float pe = npe_b2[g * CNL_ + c];
        #pragma unroll
        for (int d = 0; d < CNL_; d++) pe += h2_s[j][d] * r_npe_w2[(g * CNL_ + d) * CNL_ + c];
        int nn = inds_s[j];
        float nk = 0.f, nv2 = 0.f;
        const int row = g * CNL_ + c;
        #pragma unroll 8
        for (int cc = 0; cc < 64; cc++) {
            float a = tf32r(abs_x[(b * 64 + cc) * N_ + nn]);
            nk  += rT_Wnk[cc * NL_ + row]  * a;
            nv2 += rT_Wnv2[cc * NL_ + row] * a;
        }
        g_M[bg * CNL_ * K_ + c * K_ + j]    = nk + pe;
        g_nv2j[bg * CNL_ * K_ + c * K_ + j] = nv2;
    }
}

// ---------------- kernel 4: non-local main (smem-staged, shuffle subgroups) ----------------
struct __align__(16) NLSmem {
    float wnq[64 * 64];
    float wnv1[64 * 64];
    float wnv2[64 * 64];
    float M[G_][CNL_ * K_];
    float nv2jT[G_][K_ * CNL_];
    float tv[G_ * K_];
    float a2[64][4];
    float outbuf[64 * 65];
};

__global__ __launch_bounds__(256) void k_nl_main(
    const float* __restrict__ abs_x,
    float*       __restrict__ out)
{
    extern __shared__ char smraw[];
    NLSmem* s = (NLSmem*)smraw;

    const int blk = blockIdx.x;
    const int b   = blk / (N_ / TNL);
    const int n0  = (blk % (N_ / TNL)) * TNL;
    const int tid = threadIdx.x;
    const int warp  = tid >> 5;
    const int half  = (tid >> 4) & 1;
    const int c     = tid & 15;
    const int g     = (warp & 1) * 2 + half;
    const int nslot = warp >> 1;
    const int o     = g * CNL_ + c;

    for (int i = tid; i < 64 * 64; i += 256) {
        s->wnq[i]  = rT_Wnq[i];
        s->wnv1[i] = rT_Wnv1[i];
        s->wnv2[i] = rT_Wnv2[i];
    }
    for (int i = tid; i < G_ * CNL_ * K_; i += 256) {
        float mv = tf32r(g_M[b * G_ * CNL_ * K_ + i]);
        s->M[0][i] = mv;
        int gg = i >> 8, rem = i & 255, cc2 = rem >> 4, jj = rem & 15;
        s->nv2jT[gg][jj * 16 + cc2] = tf32r(g_nv2j[b * G_ * CNL_ * K_ + i]);
    }
    if (tid < G_ * K_) s->tv[tid] = g_tanhvals[b * G_ * K_ + tid];
    __syncthreads();

    const float tvj = s->tv[g * K_ + c];

    for (int it = 0; it < TNL / 4; it++) {
        const int nb = n0 + it * 4;
        {
            int cc = tid >> 2, nn = tid & 3;
            s->a2[cc][nn] = tf32r(abs_x[(b * 64 + cc) * N_ + nb + nn]);
        }
        __syncthreads();

        float nq = 0.f, nv1 = 0.f, nv2 = 0.f;
        #pragma unroll 8
        for (int cc = 0; cc < 64; cc++) {
            float a = s->a2[cc][nslot];
            nq  += s->wnq[cc * 64 + o]  * a;
            nv1 += s->wnv1[cc * 64 + o] * a;
            nv2 += s->wnv2[cc * 64 + o] * a;
        }
        float nqr = tf32r(nq);

        float sc = 0.f;
        const float* Mg = s->M[g];
        #pragma unroll
        for (int c2 = 0; c2 < CNL_; c2++) {
            float v = __shfl_sync(0xffffffffu, nqr, c2, 16);
            sc += v * Mg[c2 * 16 + c];
        }
        float m = -1e30f;
        #pragma unroll
        for (int j = 0; j < K_; j++) m = fmaxf(m, __shfl_sync(0xffffffffu, sc, j, 16));
        float e = expf(sc - m);
        float sum = 0.f;
        #pragma unroll
        for (int j = 0; j < K_; j++) sum += __shfl_sync(0xffffffffu, e, j, 16);
        float inv = 1.f / sum;
        float w = e * inv * tvj;
        float ws = 0.f;
        #pragma unroll
        for (int j = 0; j < K_; j++) ws += __shfl_sync(0xffffffffu, w, j, 16);

        float og = (nv1 - nv2) * ws;
        const float* nvg = s->nv2jT[g];
        #pragma unroll
        for (int j = 0; j < K_; j++) {
            float wj = tf32r(__shfl_sync(0xffffffffu, w, j, 16));
            og += wj * nvg[j * 16 + c];
        }
        s->outbuf[o * 65 + it * 4 + nslot] = og;
        __syncthreads();
    }

    for (int t = tid; t < 64 * 16; t += 256) {
        int o2 = t >> 4, q = t & 15;
        const float* rp = &s->outbuf[o2 * 65 + q * 4];
        float4 v = make_float4(rp[0], rp[1], rp[2], rp[3]);
        *(float4*)&out[((size_t)(b * COUT_ + L_ + o2)) * N_ + n0 + q * 4] = v;
    }
}

// ---------------- launcher ----------------
extern "C" void kernel_launch(void* const* d_in, const int* in_sizes, int n_in,
                              void* d_out, int out_size) {
    const float* x      = (const float*)d_in[0];
    const float* abs_x  = (const float*)d_in[1];
    const float* points = (const float*)d_in[2];
    const float* Wq     = (const float*)d_in[3];
    const float* Wk     = (const float*)d_in[4];
    const float* Wv     = (const float*)d_in[5];
    const float* Wnq    = (const float*)d_in[6];
    const float* Wnk    = (const float*)d_in[7];
    const float* Wnv1   = (const float*)d_in[8];
    const float* Wnv2   = (const float*)d_in[9];
    const float* pe_w1  = (const float*)d_in[10];
    const float* pe_b1  = (const float*)d_in[11];
    const float* pe_w2  = (const float*)d_in[12];
    const float* pe_b2  = (const float*)d_in[13];
    const float* npe_w1 = (const float*)d_in[14];
    const float* npe_b1 = (const float*)d_in[15];
    const float* npe_w2 = (const float*)d_in[16];
    const float* npe_b2 = (const float*)d_in[17];
    const int*   idx    = (const int*)d_in[18];
    float* out = (float*)d_out;

    static int smem_set = 0;
    if (!smem_set) {
        cudaFuncSetAttribute(k_local, cudaFuncAttributeMaxDynamicSharedMemorySize,
                             (int)sizeof(LocalSmem));
        cudaFuncSetAttribute(k_nl_main, cudaFuncAttributeMaxDynamicSharedMemorySize,
                             (int)sizeof(NLSmem));
        smem_set = 1;
    }

    k_prep<<<128, 256>>>(Wq, Wk, Wv, pe_w1, pe_b1, pe_w2,
                         Wnq, Wnk, Wnv1, Wnv2, npe_w1, npe_w2);
    k_local<<<B_ * (N_ / TN), THR, sizeof(LocalSmem)>>>(x, abs_x, points,
                                                        pe_b2, idx, out);
    k_topk<<<B_ * G_, 256>>>();
    k_nl_prep<<<B_ * G_, 256>>>(abs_x, points, npe_b1, npe_b2);
    k_nl_main<<<B_ * (N_ / TNL), 256, sizeof(NLSmem)>>>(abs_x, out);
}